// round 3
// baseline (speedup 1.0000x reference)
#include <cuda_runtime.h>
#include <math.h>

#define NN 256
#define DD 64
#define BB 2048
#define RANK_K 52428          // int(0.8 * 256 * 256)
#define KSPLIT 32

typedef unsigned long long ull;

// ---------------- scratch (device globals; no allocation allowed) ------------
__device__ float g_thr;
__device__ float g_adj[NN * NN];
__device__ float g_eff[NN * DD * DD];                 // 4 MB
__device__ float g_node[(size_t)BB * NN * DD];        // 128 MB
__device__ float g_parts[(size_t)KSPLIT * BB * DD];   // 16.8 MB

// ---------------- packed f32x2 helpers ---------------------------------------
__device__ __forceinline__ ull pk_dup(float a) {
    ull r; asm("mov.b64 %0, {%1, %1};" : "=l"(r) : "f"(a)); return r;
}
__device__ __forceinline__ ull pk2(float x, float y) {
    ull r; asm("mov.b64 %0, {%1, %2};" : "=l"(r) : "f"(x), "f"(y)); return r;
}
__device__ __forceinline__ void fma2(ull& d, ull a, ull b) {
    asm("fma.rn.f32x2 %0, %1, %2, %0;" : "+l"(d) : "l"(a), "l"(b));
}
__device__ __forceinline__ float2 unpk(ull v) {
    float lo, hi; asm("mov.b64 {%0, %1}, %2;" : "=f"(lo), "=f"(hi) : "l"(v));
    return make_float2(lo, hi);
}

// ---------------- helpers ----------------------------------------------------
__device__ __forceinline__ unsigned f2ord(float f) {
    unsigned u = __float_as_uint(f);
    return (u & 0x80000000u) ? ~u : (u | 0x80000000u);
}
__device__ __forceinline__ float ord2f(unsigned u) {
    u = (u & 0x80000000u) ? (u ^ 0x80000000u) : ~u;
    return __uint_as_float(u);
}
__device__ __forceinline__ float sigmoidf_(float v) {
    return 1.0f / (1.0f + expf(-v));
}

// ---------------- kernel 1: radix-select threshold ---------------------------
__global__ void kthresh(const float* __restrict__ adj_param) {
    __shared__ unsigned hist[256];
    __shared__ unsigned s_sel;
    __shared__ int s_rank;
    unsigned prefix = 0;
    int rank = RANK_K;
    const int T = NN * NN;
    for (int pass = 3; pass >= 0; --pass) {
        for (int i = threadIdx.x; i < 256; i += blockDim.x) hist[i] = 0;
        __syncthreads();
        for (int i = threadIdx.x; i < T; i += blockDim.x) {
            unsigned u = f2ord(adj_param[i]);
            unsigned hi = (pass == 3) ? 0u : (u >> ((pass + 1) * 8));
            if (hi == prefix) atomicAdd(&hist[(u >> (pass * 8)) & 0xFF], 1u);
        }
        __syncthreads();
        if (threadIdx.x == 0) {
            unsigned cum = 0, b = 0;
            for (b = 0; b < 256; b++) {
                if (cum + hist[b] > (unsigned)rank) break;
                cum += hist[b];
            }
            s_sel = b;
            s_rank = rank - (int)cum;
        }
        __syncthreads();
        prefix = (prefix << 8) | s_sel;
        rank = s_rank;
        __syncthreads();
    }
    if (threadIdx.x == 0) g_thr = sigmoidf_(ord2f(prefix));
}

// ---------------- kernel 2: adjacency build + output -------------------------
__global__ void kadj(const float* __restrict__ adj_param, float* __restrict__ out_adj) {
    int idx = blockIdx.x * blockDim.x + threadIdx.x;
    int i = idx >> 8, j = idx & 255;
    float s = sigmoidf_(adj_param[idx]);
    float a = (s > g_thr && i != j) ? s : 0.0f;
    g_adj[idx] = a;
    if (out_adj) out_adj[idx] = a;
}

// ---------------- kernel 3: effW1 = 0.5*(I + adj^T) @ G ----------------------
__global__ void keff(const float* __restrict__ gpW1) {
    __shared__ float adjs[32][36];
    __shared__ float Gs[32][132];
    int tx = threadIdx.x & 31;
    int ty = threadIdx.x >> 5;
    int de0 = blockIdx.x * 128;
    int j0 = blockIdx.y * 32;
    float acc[4][4] = {};
    for (int i0 = 0; i0 < NN; i0 += 32) {
        for (int l = threadIdx.x; l < 32 * 32; l += 256) {
            int ii = l >> 5, jj = l & 31;
            adjs[ii][jj] = g_adj[(i0 + ii) * NN + j0 + jj];
        }
        for (int l = threadIdx.x; l < 32 * 32; l += 256) {
            int ii = l >> 5, dq = (l & 31) * 4;
            float4 v = *reinterpret_cast<const float4*>(&gpW1[(size_t)(i0 + ii) * 4096 + de0 + dq]);
            *reinterpret_cast<float4*>(&Gs[ii][dq]) = v;
        }
        __syncthreads();
#pragma unroll
        for (int k = 0; k < 32; k++) {
            float4 a4 = *reinterpret_cast<const float4*>(&adjs[k][ty * 4]);
            float4 g4 = *reinterpret_cast<const float4*>(&Gs[k][tx * 4]);
            float av[4] = {a4.x, a4.y, a4.z, a4.w};
            float gv[4] = {g4.x, g4.y, g4.z, g4.w};
#pragma unroll
            for (int jj = 0; jj < 4; jj++)
#pragma unroll
                for (int dq = 0; dq < 4; dq++) acc[jj][dq] += av[jj] * gv[dq];
        }
        __syncthreads();
    }
#pragma unroll
    for (int jj = 0; jj < 4; jj++) {
        int j = j0 + ty * 4 + jj;
        int de = de0 + tx * 4;
        float4 gd = *reinterpret_cast<const float4*>(&gpW1[(size_t)j * 4096 + de]);
        float4 o;
        o.x = 0.5f * (gd.x + acc[jj][0]);
        o.y = 0.5f * (gd.y + acc[jj][1]);
        o.z = 0.5f * (gd.z + acc[jj][2]);
        o.w = 0.5f * (gd.w + acc[jj][3]);
        *reinterpret_cast<float4*>(&g_eff[(size_t)j * 4096 + de]) = o;
    }
}

// ---------------- shared FFMA2 inner GEMM: C[128x64] += Xs[128x64] @ Ws[64x64]
// Xs column-swizzled: element (r,k) stored at Xs[r*64 + (k ^ (((r>>3)&3)<<2))]
// Thread (tx,ty): rows 8*ty..8*ty+7, cols 4*tx..4*tx+3; acc[i][p] packs cols (4tx+2p, 4tx+2p+1)
__device__ __forceinline__ void mm_128x64(const float* __restrict__ Xs,
                                          const float* __restrict__ Ws,
                                          int tx, int ty, unsigned xsw,
                                          ull acc[8][2]) {
#pragma unroll 2
    for (int kq = 0; kq < 16; kq++) {
        float4 xq[8];
#pragma unroll
        for (int i = 0; i < 8; i++)
            xq[i] = *reinterpret_cast<const float4*>(&Xs[(8 * ty + i) * 64 + ((4 * kq) ^ xsw)]);
#pragma unroll
        for (int dk = 0; dk < 4; dk++) {
            float4 wv = *reinterpret_cast<const float4*>(&Ws[(4 * kq + dk) * 64 + 4 * tx]);
            ull w01 = pk2(wv.x, wv.y);
            ull w23 = pk2(wv.z, wv.w);
#pragma unroll
            for (int i = 0; i < 8; i++) {
                float a = (dk == 0) ? xq[i].x : (dk == 1) ? xq[i].y : (dk == 2) ? xq[i].z : xq[i].w;
                ull a2 = pk_dup(a);
                fma2(acc[i][0], a2, w01);
                fma2(acc[i][1], a2, w23);
            }
        }
    }
}

// ---------------- kernel 4: grouped per-node 2-layer MLP ---------------------
__global__ void __launch_bounds__(256, 2) knode(
    const float* __restrict__ x, const float* __restrict__ W1,
    const float* __restrict__ b1, const float* __restrict__ W2,
    const float* __restrict__ b2) {
    __shared__ float Xs[128 * 64];
    __shared__ float Ws[64 * 64];
    int n = blockIdx.y;
    int b0 = blockIdx.x * 128;
    int tid = threadIdx.x;
    int tx = tid & 15, ty = tid >> 4;
    unsigned xsw = (unsigned)((ty & 3) << 2);

    // fill Xs (swizzled)
#pragma unroll
    for (int m = 0; m < 8; m++) {
        int l = tid + m * 256;
        int r = l >> 4, cq = (l & 15) * 4;
        float4 v = *reinterpret_cast<const float4*>(&x[(size_t)(b0 + r) * (NN * DD) + n * DD + cq]);
        *reinterpret_cast<float4*>(&Xs[r * 64 + (cq ^ (((r >> 3) & 3) << 2))]) = v;
    }
    // fill W1
#pragma unroll
    for (int m = 0; m < 4; m++) {
        int l = tid + m * 256;
        int k = l >> 4, cq = (l & 15) * 4;
        *reinterpret_cast<float4*>(&Ws[k * 64 + cq]) =
            *reinterpret_cast<const float4*>(&W1[(size_t)n * 4096 + k * 64 + cq]);
    }
    __syncthreads();

    ull acc[8][2] = {};
    mm_128x64(Xs, Ws, tx, ty, xsw, acc);
    __syncthreads();

    // h = relu(acc + b1) back into Xs (same swizzle); load W2
    float4 bv = *reinterpret_cast<const float4*>(&b1[n * DD + 4 * tx]);
#pragma unroll
    for (int i = 0; i < 8; i++) {
        float2 p0 = unpk(acc[i][0]);
        float2 p1 = unpk(acc[i][1]);
        float4 h;
        h.x = fmaxf(p0.x + bv.x, 0.0f);
        h.y = fmaxf(p0.y + bv.y, 0.0f);
        h.z = fmaxf(p1.x + bv.z, 0.0f);
        h.w = fmaxf(p1.y + bv.w, 0.0f);
        int r = 8 * ty + i;
        *reinterpret_cast<float4*>(&Xs[r * 64 + ((4 * tx) ^ xsw)]) = h;
    }
#pragma unroll
    for (int m = 0; m < 4; m++) {
        int l = tid + m * 256;
        int k = l >> 4, cq = (l & 15) * 4;
        *reinterpret_cast<float4*>(&Ws[k * 64 + cq]) =
            *reinterpret_cast<const float4*>(&W2[(size_t)n * 4096 + k * 64 + cq]);
    }
    __syncthreads();

    ull acc2[8][2] = {};
    mm_128x64(Xs, Ws, tx, ty, xsw, acc2);

    float4 b2v = *reinterpret_cast<const float4*>(&b2[n * DD + 4 * tx]);
#pragma unroll
    for (int i = 0; i < 8; i++) {
        float2 p0 = unpk(acc2[i][0]);
        float2 p1 = unpk(acc2[i][1]);
        int r = b0 + 8 * ty + i;
        float4 o;
        o.x = p0.x + b2v.x;
        o.y = p0.y + b2v.y;
        o.z = p1.x + b2v.z;
        o.w = p1.y + b2v.w;
        *reinterpret_cast<float4*>(&g_node[(size_t)r * (NN * DD) + n * DD + 4 * tx]) = o;
    }
}

// ---------------- kernel 5: node_flat @ effW1, split-K -----------------------
__global__ void __launch_bounds__(256, 2) kgemmB() {
    __shared__ float Xs[128 * 64];
    __shared__ float Ws[64 * 64];
    int tid = threadIdx.x;
    int tx = tid & 15, ty = tid >> 4;
    unsigned xsw = (unsigned)((ty & 3) << 2);
    int b0 = blockIdx.x * 128;
    int kbase = blockIdx.y * (NN * DD / KSPLIT);   // 512 per split

    ull acc[8][2] = {};
    for (int c = 0; c < (NN * DD / KSPLIT) / 64; c++) {   // 8 chunks of 64
        int kb = kbase + c * 64;
#pragma unroll
        for (int m = 0; m < 8; m++) {
            int l = tid + m * 256;
            int r = l >> 4, cq = (l & 15) * 4;
            float4 v = *reinterpret_cast<const float4*>(&g_node[(size_t)(b0 + r) * (NN * DD) + kb + cq]);
            *reinterpret_cast<float4*>(&Xs[r * 64 + (cq ^ (((r >> 3) & 3) << 2))]) = v;
        }
#pragma unroll
        for (int m = 0; m < 4; m++) {
            int l = tid + m * 256;
            int k = l >> 4, cq = (l & 15) * 4;
            *reinterpret_cast<float4*>(&Ws[k * 64 + cq]) =
                *reinterpret_cast<const float4*>(&g_eff[(size_t)(kb + k) * 64 + cq]);
        }
        __syncthreads();
        mm_128x64(Xs, Ws, tx, ty, xsw, acc);
        __syncthreads();
    }

#pragma unroll
    for (int i = 0; i < 8; i++) {
        float2 p0 = unpk(acc[i][0]);
        float2 p1 = unpk(acc[i][1]);
        int r = b0 + 8 * ty + i;
        float4 o = {p0.x, p0.y, p1.x, p1.y};
        *reinterpret_cast<float4*>(&g_parts[((size_t)blockIdx.y * BB + r) * 64 + 4 * tx]) = o;
    }
}

// ---------------- kernel 6: reduce splits + relu + gpW2 epilogue -------------
__global__ void kfinal(const float* __restrict__ gpb1, const float* __restrict__ gpW2,
                       const float* __restrict__ gpb2, float* __restrict__ out) {
    __shared__ float gs[64][65];
    __shared__ float w2s[64][33];
    __shared__ float b2s[32];
    int b0 = blockIdx.x * 64;
    for (int l = threadIdx.x; l < 4096; l += 256) {
        int r = l >> 6, d = l & 63;
        float s = gpb1[d];
#pragma unroll
        for (int ks = 0; ks < KSPLIT; ks++) s += g_parts[((size_t)ks * BB + b0 + r) * 64 + d];
        gs[r][d] = fmaxf(s, 0.0f);
    }
    for (int l = threadIdx.x; l < 2048; l += 256) {
        int d = l >> 5, h = l & 31;
        w2s[d][h] = gpW2[l];
    }
    if (threadIdx.x < 32) b2s[threadIdx.x] = gpb2[threadIdx.x];
    __syncthreads();
    int h = threadIdx.x & 31, rg = threadIdx.x >> 5;
#pragma unroll
    for (int i = 0; i < 8; i++) {
        int r = rg * 8 + i;
        float s = b2s[h];
#pragma unroll 16
        for (int d = 0; d < 64; d++) s += gs[r][d] * w2s[d][h];
        out[(size_t)(b0 + r) * 32 + h] = s;
    }
}

// ---------------- launch ------------------------------------------------------
extern "C" void kernel_launch(void* const* d_in, const int* in_sizes, int n_in,
                              void* d_out, int out_size) {
    const float* x         = (const float*)d_in[0];
    const float* adj_param = (const float*)d_in[1];
    const float* W1        = (const float*)d_in[2];
    const float* b1        = (const float*)d_in[3];
    const float* W2        = (const float*)d_in[4];
    const float* b2        = (const float*)d_in[5];
    const float* gpW1      = (const float*)d_in[6];
    const float* gpb1      = (const float*)d_in[7];
    const float* gpW2      = (const float*)d_in[8];
    const float* gpb2      = (const float*)d_in[9];
    float* out = (float*)d_out;
    float* adj_out = (out_size >= 131072) ? (out + BB * 32) : nullptr;

    kthresh<<<1, 1024>>>(adj_param);
    kadj<<<64, 1024>>>(adj_param, adj_out);
    keff<<<dim3(32, 8), 256>>>(gpW1);
    knode<<<dim3(BB / 128, NN), 256>>>(x, W1, b1, W2, b2);
    kgemmB<<<dim3(BB / 128, KSPLIT), 256>>>();
    kfinal<<<BB / 64, 256>>>(gpb1, gpW2, gpb2, out);
}

// round 4
// speedup vs baseline: 1.0447x; 1.0447x over previous
#include <cuda_runtime.h>
#include <math.h>

#define NN 256
#define DD 64
#define BB 2048
#define RANK_K 52428          // int(0.8 * 256 * 256)
#define KSPLIT 32

typedef unsigned long long ull;

// ---------------- scratch (device globals; no allocation allowed) ------------
__device__ float g_thr;
__device__ float g_adj[NN * NN];
__device__ float g_eff[NN * DD * DD];                 // 4 MB
__device__ float g_node[(size_t)BB * NN * DD];        // 128 MB
__device__ float g_parts[(size_t)KSPLIT * BB * DD];   // 16.8 MB

// ---------------- packed f32x2 helpers ---------------------------------------
__device__ __forceinline__ ull pk_dup(float a) {
    ull r; asm("mov.b64 %0, {%1, %1};" : "=l"(r) : "f"(a)); return r;
}
__device__ __forceinline__ void fma2(ull& d, ull a, ull b) {
    asm("fma.rn.f32x2 %0, %1, %2, %0;" : "+l"(d) : "l"(a), "l"(b));
}
__device__ __forceinline__ float2 unpk(ull v) {
    float lo, hi; asm("mov.b64 {%0, %1}, %2;" : "=f"(lo), "=f"(hi) : "l"(v));
    return make_float2(lo, hi);
}

// ---------------- misc helpers ------------------------------------------------
__device__ __forceinline__ unsigned f2ord(float f) {
    unsigned u = __float_as_uint(f);
    return (u & 0x80000000u) ? ~u : (u | 0x80000000u);
}
__device__ __forceinline__ float ord2f(unsigned u) {
    u = (u & 0x80000000u) ? (u ^ 0x80000000u) : ~u;
    return __uint_as_float(u);
}
__device__ __forceinline__ float sigmoidf_(float v) {
    return 1.0f / (1.0f + expf(-v));
}

// ---------------- kernel 1: radix-select threshold ---------------------------
__global__ void kthresh(const float* __restrict__ adj_param) {
    __shared__ unsigned hist[256];
    __shared__ unsigned s_sel;
    __shared__ int s_rank;
    unsigned prefix = 0;
    int rank = RANK_K;
    const int T = NN * NN;
    for (int pass = 3; pass >= 0; --pass) {
        for (int i = threadIdx.x; i < 256; i += blockDim.x) hist[i] = 0;
        __syncthreads();
        for (int i = threadIdx.x; i < T; i += blockDim.x) {
            unsigned u = f2ord(adj_param[i]);
            unsigned hi = (pass == 3) ? 0u : (u >> ((pass + 1) * 8));
            if (hi == prefix) atomicAdd(&hist[(u >> (pass * 8)) & 0xFF], 1u);
        }
        __syncthreads();
        if (threadIdx.x == 0) {
            unsigned cum = 0, b = 0;
            for (b = 0; b < 256; b++) {
                if (cum + hist[b] > (unsigned)rank) break;
                cum += hist[b];
            }
            s_sel = b;
            s_rank = rank - (int)cum;
        }
        __syncthreads();
        prefix = (prefix << 8) | s_sel;
        rank = s_rank;
        __syncthreads();
    }
    if (threadIdx.x == 0) g_thr = sigmoidf_(ord2f(prefix));
}

// ---------------- kernel 2: adjacency build + output -------------------------
__global__ void kadj(const float* __restrict__ adj_param, float* __restrict__ out_adj) {
    int idx = blockIdx.x * blockDim.x + threadIdx.x;
    int i = idx >> 8, j = idx & 255;
    float s = sigmoidf_(adj_param[idx]);
    float a = (s > g_thr && i != j) ? s : 0.0f;
    g_adj[idx] = a;
    if (out_adj) out_adj[idx] = a;
}

// ---------------- kernel 3: effW1 = 0.5*(I + adj^T) @ G ----------------------
__global__ void keff(const float* __restrict__ gpW1) {
    __shared__ float adjs[32][36];
    __shared__ float Gs[32][132];
    int tx = threadIdx.x & 31;
    int ty = threadIdx.x >> 5;
    int de0 = blockIdx.x * 128;
    int j0 = blockIdx.y * 32;
    float acc[4][4] = {};
    for (int i0 = 0; i0 < NN; i0 += 32) {
        for (int l = threadIdx.x; l < 32 * 32; l += 256) {
            int ii = l >> 5, jj = l & 31;
            adjs[ii][jj] = g_adj[(i0 + ii) * NN + j0 + jj];
        }
        for (int l = threadIdx.x; l < 32 * 32; l += 256) {
            int ii = l >> 5, dq = (l & 31) * 4;
            float4 v = *reinterpret_cast<const float4*>(&gpW1[(size_t)(i0 + ii) * 4096 + de0 + dq]);
            *reinterpret_cast<float4*>(&Gs[ii][dq]) = v;
        }
        __syncthreads();
#pragma unroll
        for (int k = 0; k < 32; k++) {
            float4 a4 = *reinterpret_cast<const float4*>(&adjs[k][ty * 4]);
            float4 g4 = *reinterpret_cast<const float4*>(&Gs[k][tx * 4]);
            float av[4] = {a4.x, a4.y, a4.z, a4.w};
            float gv[4] = {g4.x, g4.y, g4.z, g4.w};
#pragma unroll
            for (int jj = 0; jj < 4; jj++)
#pragma unroll
                for (int dq = 0; dq < 4; dq++) acc[jj][dq] += av[jj] * gv[dq];
        }
        __syncthreads();
    }
#pragma unroll
    for (int jj = 0; jj < 4; jj++) {
        int j = j0 + ty * 4 + jj;
        int de = de0 + tx * 4;
        float4 gd = *reinterpret_cast<const float4*>(&gpW1[(size_t)j * 4096 + de]);
        float4 o;
        o.x = 0.5f * (gd.x + acc[jj][0]);
        o.y = 0.5f * (gd.y + acc[jj][1]);
        o.z = 0.5f * (gd.z + acc[jj][2]);
        o.w = 0.5f * (gd.w + acc[jj][3]);
        *reinterpret_cast<float4*>(&g_eff[(size_t)j * 4096 + de]) = o;
    }
}

// ---------------- FFMA2 inner GEMM: C[128x64] += Xs[128x64] @ Ws[64x64] ------
// 128 threads. tx = tid&7 (cols {4tx..4tx+3} and {32+4tx..32+4tx+3}),
// ty = tid>>3 (rows 8ty..8ty+7).
// Xs swizzled: x[r][c] at Xs[r*64 + (c ^ (((r>>3)&3)<<2))].
// acc[i][0..1] = cols (4tx,4tx+1),(4tx+2,4tx+3); acc[i][2..3] = +32 versions.
__device__ __forceinline__ void mm_128x64(const float* __restrict__ Xs,
                                          const float* __restrict__ Ws,
                                          int tx, int ty, unsigned xsw,
                                          ull acc[8][4]) {
#pragma unroll 2
    for (int kq = 0; kq < 16; kq++) {
        float4 xq[8];
#pragma unroll
        for (int i = 0; i < 8; i++)
            xq[i] = *reinterpret_cast<const float4*>(&Xs[(8 * ty + i) * 64 + ((4 * kq) ^ xsw)]);
#pragma unroll
        for (int dk = 0; dk < 4; dk++) {
            int k = 4 * kq + dk;
            ulonglong2 wA = *reinterpret_cast<const ulonglong2*>(&Ws[k * 64 + 4 * tx]);
            ulonglong2 wB = *reinterpret_cast<const ulonglong2*>(&Ws[k * 64 + 32 + 4 * tx]);
#pragma unroll
            for (int i = 0; i < 8; i++) {
                float a = (dk == 0) ? xq[i].x : (dk == 1) ? xq[i].y : (dk == 2) ? xq[i].z : xq[i].w;
                ull a2 = pk_dup(a);
                fma2(acc[i][0], a2, wA.x);
                fma2(acc[i][1], a2, wA.y);
                fma2(acc[i][2], a2, wB.x);
                fma2(acc[i][3], a2, wB.y);
            }
        }
    }
}

// ---------------- kernel 4: grouped per-node 2-layer MLP ---------------------
__global__ void __launch_bounds__(128, 4) knode(
    const float* __restrict__ x, const float* __restrict__ W1,
    const float* __restrict__ b1, const float* __restrict__ W2,
    const float* __restrict__ b2) {
    __shared__ __align__(16) float Xs[128 * 64];
    __shared__ __align__(16) float Ws[64 * 64];
    int n = blockIdx.y;
    int b0 = blockIdx.x * 128;
    int tid = threadIdx.x;
    int tx = tid & 7, ty = tid >> 3;
    unsigned xsw = (unsigned)((ty & 3) << 2);

    // fill Xs (swizzled): 2048 float4s, 16 per thread
#pragma unroll
    for (int m = 0; m < 16; m++) {
        int l = tid + m * 128;
        int r = l >> 4, cq = (l & 15) * 4;
        float4 v = *reinterpret_cast<const float4*>(&x[(size_t)(b0 + r) * (NN * DD) + n * DD + cq]);
        *reinterpret_cast<float4*>(&Xs[r * 64 + (cq ^ (((r >> 3) & 3) << 2))]) = v;
    }
    // fill W1: 1024 float4s, 8 per thread
#pragma unroll
    for (int m = 0; m < 8; m++) {
        int l = tid + m * 128;
        int k = l >> 4, cq = (l & 15) * 4;
        *reinterpret_cast<float4*>(&Ws[k * 64 + cq]) =
            *reinterpret_cast<const float4*>(&W1[(size_t)n * 4096 + k * 64 + cq]);
    }
    __syncthreads();

    ull acc[8][4] = {};
    mm_128x64(Xs, Ws, tx, ty, xsw, acc);
    __syncthreads();

    // h = relu(acc + b1) back into Xs (swizzled); reload Ws with W2
    float4 bA = *reinterpret_cast<const float4*>(&b1[n * DD + 4 * tx]);
    float4 bB = *reinterpret_cast<const float4*>(&b1[n * DD + 32 + 4 * tx]);
#pragma unroll
    for (int i = 0; i < 8; i++) {
        int r = 8 * ty + i;
        float2 p0 = unpk(acc[i][0]);
        float2 p1 = unpk(acc[i][1]);
        float2 p2 = unpk(acc[i][2]);
        float2 p3 = unpk(acc[i][3]);
        float4 hA = {fmaxf(p0.x + bA.x, 0.0f), fmaxf(p0.y + bA.y, 0.0f),
                     fmaxf(p1.x + bA.z, 0.0f), fmaxf(p1.y + bA.w, 0.0f)};
        float4 hB = {fmaxf(p2.x + bB.x, 0.0f), fmaxf(p2.y + bB.y, 0.0f),
                     fmaxf(p3.x + bB.z, 0.0f), fmaxf(p3.y + bB.w, 0.0f)};
        *reinterpret_cast<float4*>(&Xs[r * 64 + ((4 * tx) ^ xsw)]) = hA;
        *reinterpret_cast<float4*>(&Xs[r * 64 + ((32 + 4 * tx) ^ xsw)]) = hB;
    }
#pragma unroll
    for (int m = 0; m < 8; m++) {
        int l = tid + m * 128;
        int k = l >> 4, cq = (l & 15) * 4;
        *reinterpret_cast<float4*>(&Ws[k * 64 + cq]) =
            *reinterpret_cast<const float4*>(&W2[(size_t)n * 4096 + k * 64 + cq]);
    }
    __syncthreads();

    ull acc2[8][4] = {};
    mm_128x64(Xs, Ws, tx, ty, xsw, acc2);

    float4 cA = *reinterpret_cast<const float4*>(&b2[n * DD + 4 * tx]);
    float4 cB = *reinterpret_cast<const float4*>(&b2[n * DD + 32 + 4 * tx]);
#pragma unroll
    for (int i = 0; i < 8; i++) {
        int r = b0 + 8 * ty + i;
        float2 p0 = unpk(acc2[i][0]);
        float2 p1 = unpk(acc2[i][1]);
        float2 p2 = unpk(acc2[i][2]);
        float2 p3 = unpk(acc2[i][3]);
        float4 oA = {p0.x + cA.x, p0.y + cA.y, p1.x + cA.z, p1.y + cA.w};
        float4 oB = {p2.x + cB.x, p2.y + cB.y, p3.x + cB.z, p3.y + cB.w};
        *reinterpret_cast<float4*>(&g_node[(size_t)r * (NN * DD) + n * DD + 4 * tx]) = oA;
        *reinterpret_cast<float4*>(&g_node[(size_t)r * (NN * DD) + n * DD + 32 + 4 * tx]) = oB;
    }
}

// ---------------- kernel 5: node_flat @ effW1, split-K -----------------------
__global__ void __launch_bounds__(128, 4) kgemmB() {
    __shared__ __align__(16) float Xs[128 * 64];
    __shared__ __align__(16) float Ws[64 * 64];
    int tid = threadIdx.x;
    int tx = tid & 7, ty = tid >> 3;
    unsigned xsw = (unsigned)((ty & 3) << 2);
    int b0 = blockIdx.x * 128;
    int kbase = blockIdx.y * (NN * DD / KSPLIT);   // 512 per split

    ull acc[8][4] = {};
    for (int c = 0; c < (NN * DD / KSPLIT) / 64; c++) {   // 8 chunks of 64
        int kb = kbase + c * 64;
#pragma unroll
        for (int m = 0; m < 16; m++) {
            int l = tid + m * 128;
            int r = l >> 4, cq = (l & 15) * 4;
            float4 v = *reinterpret_cast<const float4*>(&g_node[(size_t)(b0 + r) * (NN * DD) + kb + cq]);
            *reinterpret_cast<float4*>(&Xs[r * 64 + (cq ^ (((r >> 3) & 3) << 2))]) = v;
        }
#pragma unroll
        for (int m = 0; m < 8; m++) {
            int l = tid + m * 128;
            int k = l >> 4, cq = (l & 15) * 4;
            *reinterpret_cast<float4*>(&Ws[k * 64 + cq]) =
                *reinterpret_cast<const float4*>(&g_eff[(size_t)(kb + k) * 64 + cq]);
        }
        __syncthreads();
        mm_128x64(Xs, Ws, tx, ty, xsw, acc);
        __syncthreads();
    }

#pragma unroll
    for (int i = 0; i < 8; i++) {
        int r = b0 + 8 * ty + i;
        float2 p0 = unpk(acc[i][0]);
        float2 p1 = unpk(acc[i][1]);
        float2 p2 = unpk(acc[i][2]);
        float2 p3 = unpk(acc[i][3]);
        float4 oA = {p0.x, p0.y, p1.x, p1.y};
        float4 oB = {p2.x, p2.y, p3.x, p3.y};
        size_t base = ((size_t)blockIdx.y * BB + r) * 64;
        *reinterpret_cast<float4*>(&g_parts[base + 4 * tx]) = oA;
        *reinterpret_cast<float4*>(&g_parts[base + 32 + 4 * tx]) = oB;
    }
}

// ---------------- kernel 6: reduce splits + relu + gpW2 epilogue -------------
__global__ void kfinal(const float* __restrict__ gpb1, const float* __restrict__ gpW2,
                       const float* __restrict__ gpb2, float* __restrict__ out) {
    __shared__ float gs[64][65];
    __shared__ float w2s[64][33];
    __shared__ float b2s[32];
    int b0 = blockIdx.x * 64;
    for (int l = threadIdx.x; l < 4096; l += 256) {
        int r = l >> 6, d = l & 63;
        float s = gpb1[d];
#pragma unroll
        for (int ks = 0; ks < KSPLIT; ks++) s += g_parts[((size_t)ks * BB + b0 + r) * 64 + d];
        gs[r][d] = fmaxf(s, 0.0f);
    }
    for (int l = threadIdx.x; l < 2048; l += 256) {
        int d = l >> 5, h = l & 31;
        w2s[d][h] = gpW2[l];
    }
    if (threadIdx.x < 32) b2s[threadIdx.x] = gpb2[threadIdx.x];
    __syncthreads();
    int h = threadIdx.x & 31, rg = threadIdx.x >> 5;
#pragma unroll
    for (int i = 0; i < 8; i++) {
        int r = rg * 8 + i;
        float s = b2s[h];
#pragma unroll 16
        for (int d = 0; d < 64; d++) s += gs[r][d] * w2s[d][h];
        out[(size_t)(b0 + r) * 32 + h] = s;
    }
}

// ---------------- launch ------------------------------------------------------
extern "C" void kernel_launch(void* const* d_in, const int* in_sizes, int n_in,
                              void* d_out, int out_size) {
    const float* x         = (const float*)d_in[0];
    const float* adj_param = (const float*)d_in[1];
    const float* W1        = (const float*)d_in[2];
    const float* b1        = (const float*)d_in[3];
    const float* W2        = (const float*)d_in[4];
    const float* b2        = (const float*)d_in[5];
    const float* gpW1      = (const float*)d_in[6];
    const float* gpb1      = (const float*)d_in[7];
    const float* gpW2      = (const float*)d_in[8];
    const float* gpb2      = (const float*)d_in[9];
    float* out = (float*)d_out;
    float* adj_out = (out_size >= 131072) ? (out + BB * 32) : nullptr;

    kthresh<<<1, 1024>>>(adj_param);
    kadj<<<64, 1024>>>(adj_param, adj_out);
    keff<<<dim3(32, 8), 256>>>(gpW1);
    knode<<<dim3(BB / 128, NN), 128>>>(x, W1, b1, W2, b2);
    kgemmB<<<dim3(BB / 128, KSPLIT), 128>>>();
    kfinal<<<BB / 64, 256>>>(gpb1, gpW2, gpb2, out);
}